// round 1
// baseline (speedup 1.0000x reference)
#include <cuda_runtime.h>
#include <math.h>

#define BATCH 2
#define SEQ   2048
#define EMB   1024
#define NHEADS 16
#define HDIM  64
#define FF    4096
#define MTOT  (BATCH*SEQ)   /* 4096 rows */

// ---------------- scratch (device globals: allocation-free) ----------------
__device__ float g_h  [MTOT*EMB];   // LN output (reused for LN1 and LN2)
__device__ float g_q  [MTOT*EMB];
__device__ float g_k  [MTOT*EMB];
__device__ float g_v  [MTOT*EMB];
__device__ float g_ctx[MTOT*EMB];
__device__ float g_x2 [MTOT*EMB];   // x + attn_out (residual 1)
__device__ float g_ff [(size_t)MTOT*FF];

// ---------------- LayerNorm (ddof=1), one block per row ----------------
__global__ __launch_bounds__(256)
void ln_kernel(const float* __restrict__ x, const float* __restrict__ sc,
               const float* __restrict__ sh, float* __restrict__ out)
{
    int row = blockIdx.x;
    const float* xr = x + (size_t)row * EMB;
    int t = threadIdx.x;

    float4 v4 = *(const float4*)(xr + t * 4);
    float v[4] = {v4.x, v4.y, v4.z, v4.w};

    __shared__ float red[8];
    // --- mean ---
    float s = v[0] + v[1] + v[2] + v[3];
    #pragma unroll
    for (int o = 16; o; o >>= 1) s += __shfl_xor_sync(0xffffffffu, s, o);
    if ((t & 31) == 0) red[t >> 5] = s;
    __syncthreads();
    float tot = 0.f;
    #pragma unroll
    for (int i = 0; i < 8; i++) tot += red[i];
    float mean = tot * (1.0f / EMB);
    __syncthreads();

    // --- variance (unbiased, /1023) ---
    float sq = 0.f;
    #pragma unroll
    for (int i = 0; i < 4; i++) { float d = v[i] - mean; sq += d * d; }
    #pragma unroll
    for (int o = 16; o; o >>= 1) sq += __shfl_xor_sync(0xffffffffu, sq, o);
    if ((t & 31) == 0) red[t >> 5] = sq;
    __syncthreads();
    float sqt = 0.f;
    #pragma unroll
    for (int i = 0; i < 8; i++) sqt += red[i];
    float var  = sqt * (1.0f / (EMB - 1));
    float rstd = rsqrtf(var + 1e-5f);

    float4 o4;
    float* ov = &o4.x;
    #pragma unroll
    for (int i = 0; i < 4; i++) {
        int c = t * 4 + i;
        ov[i] = sc[c] * (v[i] - mean) * rstd + sh[c];
    }
    *(float4*)(out + (size_t)row * EMB + t * 4) = o4;
}

// ---------------- SGEMM 128x128x16, 256 threads, 8x8 per thread ----------------
// C[M,N] = A[M,K] @ B[K,N] + bias  (+res | gelu)   all row-major, dims % 128 == 0
// mode 0: +bias    mode 1: +bias+res    mode 2: gelu(+bias)
__global__ __launch_bounds__(256)
void sgemm_kernel(const float* __restrict__ A, const float* __restrict__ B,
                  const float* __restrict__ bias, const float* __restrict__ res,
                  float* __restrict__ C, int M, int N, int K, int mode)
{
    const int BK = 16;
    __shared__ float As[BK][128];
    __shared__ float Bs[BK][128];

    int tid = threadIdx.x;
    int tx = tid & 15, ty = tid >> 4;
    int brow = blockIdx.y * 128;
    int bcol = blockIdx.x * 128;

    float acc[8][8] = {};

    const float* Aptr = A + (size_t)brow * K;
    const float* Bptr = B + bcol;

    for (int k0 = 0; k0 < K; k0 += BK) {
        // A tile 128x16 (store transposed): 512 float4, 2 per thread
        #pragma unroll
        for (int u = 0; u < 2; u++) {
            int idx = tid + u * 256;
            int r = idx >> 2, c4 = (idx & 3) * 4;
            float4 a = *(const float4*)(Aptr + (size_t)r * K + k0 + c4);
            As[c4 + 0][r] = a.x; As[c4 + 1][r] = a.y;
            As[c4 + 2][r] = a.z; As[c4 + 3][r] = a.w;
        }
        // B tile 16x128: 512 float4, 2 per thread
        #pragma unroll
        for (int u = 0; u < 2; u++) {
            int idx = tid + u * 256;
            int r = idx >> 5, c4 = (idx & 31) * 4;
            *(float4*)&Bs[r][c4] = *(const float4*)(Bptr + (size_t)(k0 + r) * N + c4);
        }
        __syncthreads();

        #pragma unroll
        for (int kk = 0; kk < BK; kk++) {
            float ra[8], rb[8];
            #pragma unroll
            for (int i = 0; i < 8; i++) ra[i] = As[kk][ty * 8 + i];
            #pragma unroll
            for (int j = 0; j < 8; j++) rb[j] = Bs[kk][tx * 8 + j];
            #pragma unroll
            for (int i = 0; i < 8; i++)
                #pragma unroll
                for (int j = 0; j < 8; j++)
                    acc[i][j] += ra[i] * rb[j];
        }
        __syncthreads();
    }

    // epilogue
    #pragma unroll
    for (int i = 0; i < 8; i++) {
        int r = brow + ty * 8 + i;
        #pragma unroll
        for (int j4 = 0; j4 < 2; j4++) {
            float4 o4;
            float* ov = &o4.x;
            #pragma unroll
            for (int u = 0; u < 4; u++) {
                int j = j4 * 4 + u;
                int c = bcol + tx * 8 + j;
                float val = acc[i][j] + bias[c];
                if (mode == 1) {
                    val += res[(size_t)r * N + c];
                } else if (mode == 2) {
                    float xg = val;
                    val = 0.5f * xg * (1.f + tanhf(0.7978845608028654f *
                                                   (xg + 0.044715f * xg * xg * xg)));
                }
                ov[u] = val;
            }
            *(float4*)(C + (size_t)r * N + bcol + tx * 8 + j4 * 4) = o4;
        }
    }
}

// ---------------- Causal flash attention, fp32 ----------------
// Q/K/V/O layout: [token, EMB] with token = b*SEQ+s, column = head*64+d.
// Block: 256 threads = 16x16 grid; handles 64 query rows of one (b, head).
// Key tiles of 32; thread (tx,ty) owns queries ty*4..+3, dims tx*4..+3,
// and keys tx*2..+1 for the score matrix.
__global__ __launch_bounds__(256)
void attn_kernel(const float* __restrict__ Q, const float* __restrict__ K,
                 const float* __restrict__ V, float* __restrict__ O)
{
    __shared__ float Qs[64][65];
    __shared__ float Ks[32][65];
    __shared__ float Vs[32][64];
    __shared__ float Ps[64][33];

    int tid = threadIdx.x;
    int tx = tid & 15, ty = tid >> 4;
    int qb = blockIdx.x, h = blockIdx.y, b = blockIdx.z;
    size_t base = ((size_t)b * SEQ) * EMB + h * HDIM;
    const float scale = 0.125f;  // 1/sqrt(64)

    // load Q tile (pre-scaled)
    #pragma unroll
    for (int u = 0; u < 4; u++) {
        int idx = tid + u * 256;           // 0..1023
        int r = idx >> 4, c = (idx & 15) * 4;
        float4 qv = *(const float4*)(Q + base + (size_t)(qb * 64 + r) * EMB + c);
        Qs[r][c + 0] = qv.x * scale; Qs[r][c + 1] = qv.y * scale;
        Qs[r][c + 2] = qv.z * scale; Qs[r][c + 3] = qv.w * scale;
    }

    float m_i[4], l_i[4], acc[4][4];
    #pragma unroll
    for (int i = 0; i < 4; i++) {
        m_i[i] = -1e30f; l_i[i] = 0.f;
        #pragma unroll
        for (int j = 0; j < 4; j++) acc[i][j] = 0.f;
    }

    int nkb = qb * 2 + 2;   // key tiles of 32 covering keys <= qb*64+63
    for (int kb = 0; kb < nkb; kb++) {
        __syncthreads();    // protects Ks/Vs/Ps reuse (and Qs on first iter)
        // load K,V tiles 32x64
        #pragma unroll
        for (int u = 0; u < 2; u++) {
            int idx = tid + u * 256;       // 0..511
            int r = idx >> 4, c = (idx & 15) * 4;
            size_t g = base + (size_t)(kb * 32 + r) * EMB + c;
            float4 kv = *(const float4*)(K + g);
            Ks[r][c + 0] = kv.x; Ks[r][c + 1] = kv.y;
            Ks[r][c + 2] = kv.z; Ks[r][c + 3] = kv.w;
            *(float4*)&Vs[r][c] = *(const float4*)(V + g);
        }
        __syncthreads();

        // S = Q K^T : each thread 4 queries x 2 keys
        float s[4][2] = {};
        #pragma unroll
        for (int d = 0; d < 64; d++) {
            float qa[4], kr[2];
            #pragma unroll
            for (int i = 0; i < 4; i++) qa[i] = Qs[ty * 4 + i][d];
            #pragma unroll
            for (int j = 0; j < 2; j++) kr[j] = Ks[tx * 2 + j][d];
            #pragma unroll
            for (int i = 0; i < 4; i++)
                #pragma unroll
                for (int j = 0; j < 2; j++)
                    s[i][j] += qa[i] * kr[j];
        }
        // causal mask
        #pragma unroll
        for (int i = 0; i < 4; i++)
            #pragma unroll
            for (int j = 0; j < 2; j++) {
                int qq = qb * 64 + ty * 4 + i;
                int kk = kb * 32 + tx * 2 + j;
                if (kk > qq) s[i][j] = -1e30f;
            }
        // online softmax update (reduce over the 16 tx lanes)
        #pragma unroll
        for (int i = 0; i < 4; i++) {
            float mm = fmaxf(s[i][0], s[i][1]);
            #pragma unroll
            for (int o = 1; o < 16; o <<= 1)
                mm = fmaxf(mm, __shfl_xor_sync(0xffffffffu, mm, o));
            float mnew = fmaxf(m_i[i], mm);
            float p0 = __expf(s[i][0] - mnew);
            float p1 = __expf(s[i][1] - mnew);
            float rs = p0 + p1;
            #pragma unroll
            for (int o = 1; o < 16; o <<= 1)
                rs += __shfl_xor_sync(0xffffffffu, rs, o);
            float alpha = __expf(m_i[i] - mnew);
            l_i[i] = l_i[i] * alpha + rs;
            m_i[i] = mnew;
            #pragma unroll
            for (int j = 0; j < 4; j++) acc[i][j] *= alpha;
            Ps[ty * 4 + i][tx * 2 + 0] = p0;
            Ps[ty * 4 + i][tx * 2 + 1] = p1;
        }
        __syncthreads();
        // acc += P @ V
        #pragma unroll
        for (int k2 = 0; k2 < 32; k2++) {
            float pr[4], vr[4];
            #pragma unroll
            for (int i = 0; i < 4; i++) pr[i] = Ps[ty * 4 + i][k2];
            #pragma unroll
            for (int j = 0; j < 4; j++) vr[j] = Vs[k2][tx * 4 + j];
            #pragma unroll
            for (int i = 0; i < 4; i++)
                #pragma unroll
                for (int j = 0; j < 4; j++)
                    acc[i][j] += pr[i] * vr[j];
        }
    }

    // write ctx
    #pragma unroll
    for (int i = 0; i < 4; i++) {
        float inv = 1.0f / l_i[i];
        float4 o4 = { acc[i][0] * inv, acc[i][1] * inv,
                      acc[i][2] * inv, acc[i][3] * inv };
        *(float4*)(O + base + (size_t)(qb * 64 + ty * 4 + i) * EMB + tx * 4) = o4;
    }
}

// ---------------- launch ----------------
extern "C" void kernel_launch(void* const* d_in, const int* in_sizes, int n_in,
                              void* d_out, int out_size)
{
    const float* x         = (const float*)d_in[0];
    const float* Wq        = (const float*)d_in[1];
    const float* bq        = (const float*)d_in[2];
    const float* Wk        = (const float*)d_in[3];
    const float* bk        = (const float*)d_in[4];
    const float* Wv        = (const float*)d_in[5];
    const float* bv        = (const float*)d_in[6];
    const float* Wo        = (const float*)d_in[7];
    const float* bo        = (const float*)d_in[8];
    const float* W1        = (const float*)d_in[9];
    const float* b1        = (const float*)d_in[10];
    const float* W2        = (const float*)d_in[11];
    const float* b2        = (const float*)d_in[12];
    const float* ln1_scale = (const float*)d_in[13];
    const float* ln1_shift = (const float*)d_in[14];
    const float* ln2_scale = (const float*)d_in[15];
    const float* ln2_shift = (const float*)d_in[16];
    float* out = (float*)d_out;

    float *h, *q, *k, *v, *ctx, *x2, *ff;
    cudaGetSymbolAddress((void**)&h,   g_h);
    cudaGetSymbolAddress((void**)&q,   g_q);
    cudaGetSymbolAddress((void**)&k,   g_k);
    cudaGetSymbolAddress((void**)&v,   g_v);
    cudaGetSymbolAddress((void**)&ctx, g_ctx);
    cudaGetSymbolAddress((void**)&x2,  g_x2);
    cudaGetSymbolAddress((void**)&ff,  g_ff);

    dim3 gE(EMB / 128, MTOT / 128);   // N=1024 GEMMs
    dim3 gF(FF  / 128, MTOT / 128);   // N=4096 GEMM
    dim3 gA(SEQ / 64, NHEADS, BATCH);

    // 1) h = LN1(x)
    ln_kernel<<<MTOT, 256>>>(x, ln1_scale, ln1_shift, h);
    // 2-4) q,k,v = h@W + b
    sgemm_kernel<<<gE, 256>>>(h, Wq, bq, nullptr, q, MTOT, EMB, EMB, 0);
    sgemm_kernel<<<gE, 256>>>(h, Wk, bk, nullptr, k, MTOT, EMB, EMB, 0);
    sgemm_kernel<<<gE, 256>>>(h, Wv, bv, nullptr, v, MTOT, EMB, EMB, 0);
    // 5) ctx = causal_attn(q,k,v)
    attn_kernel<<<gA, 256>>>(q, k, v, ctx);
    // 6) x2 = x + ctx@Wo + bo
    sgemm_kernel<<<gE, 256>>>(ctx, Wo, bo, x, x2, MTOT, EMB, EMB, 1);
    // 7) h = LN2(x2)
    ln_kernel<<<MTOT, 256>>>(x2, ln2_scale, ln2_shift, h);
    // 8) ff = gelu(h@W1 + b1)
    sgemm_kernel<<<gF, 256>>>(h, W1, b1, nullptr, ff, MTOT, FF, EMB, 2);
    // 9) out = x2 + ff@W2 + b2
    sgemm_kernel<<<gE, 256>>>(ff, W2, b2, x2, out, MTOT, EMB, FF, 1);
}

// round 3
// speedup vs baseline: 1.8594x; 1.8594x over previous
#include <cuda_runtime.h>
#include <math.h>
#include <stdint.h>

#define BATCH 2
#define SEQ   2048
#define EMB   1024
#define NHEADS 16
#define HDIM  64
#define FF    4096
#define MTOT  (BATCH*SEQ)   /* 4096 rows */

__device__ __forceinline__ uint32_t f2tf32(float x) {
    uint32_t y;
    asm("cvt.rna.tf32.f32 %0, %1;" : "=r"(y) : "f"(x));
    return y;
}
__device__ __forceinline__ void mma_tf32(float c[4],
    uint32_t a0, uint32_t a1, uint32_t a2, uint32_t a3,
    uint32_t b0, uint32_t b1)
{
    asm volatile("mma.sync.aligned.m16n8k8.row.col.f32.tf32.tf32.f32 "
        "{%0,%1,%2,%3}, {%4,%5,%6,%7}, {%8,%9}, {%0,%1,%2,%3};"
        : "+f"(c[0]), "+f"(c[1]), "+f"(c[2]), "+f"(c[3])
        : "r"(a0), "r"(a1), "r"(a2), "r"(a3), "r"(b0), "r"(b1));
}

// ================= scratch (device globals) =================
__device__ float g_h  [MTOT*EMB];
__device__ float g_q  [MTOT*EMB];
__device__ float g_k  [MTOT*EMB];
__device__ float g_v  [MTOT*EMB];
__device__ float g_ctx[MTOT*EMB];
__device__ float g_x2 [MTOT*EMB];
__device__ float g_ff [(size_t)MTOT*FF];
// transposed tf32-rounded weights, [N][K]
__device__ uint32_t g_wtq[EMB*EMB];
__device__ uint32_t g_wtk[EMB*EMB];
__device__ uint32_t g_wtv[EMB*EMB];
__device__ uint32_t g_wto[EMB*EMB];
__device__ uint32_t g_wt1[(size_t)FF*EMB];
__device__ uint32_t g_wt2[(size_t)EMB*FF];

// ================= LayerNorm (ddof=1) =================
__global__ __launch_bounds__(256)
void ln_kernel(const float* __restrict__ x, const float* __restrict__ sc,
               const float* __restrict__ sh, float* __restrict__ out)
{
    int row = blockIdx.x;
    const float* xr = x + (size_t)row * EMB;
    int t = threadIdx.x;
    float4 v4 = *(const float4*)(xr + t * 4);
    float v[4] = {v4.x, v4.y, v4.z, v4.w};
    __shared__ float red[8];
    float s = v[0] + v[1] + v[2] + v[3];
    #pragma unroll
    for (int o = 16; o; o >>= 1) s += __shfl_xor_sync(0xffffffffu, s, o);
    if ((t & 31) == 0) red[t >> 5] = s;
    __syncthreads();
    float tot = 0.f;
    #pragma unroll
    for (int i = 0; i < 8; i++) tot += red[i];
    float mean = tot * (1.0f / EMB);
    __syncthreads();
    float sq = 0.f;
    #pragma unroll
    for (int i = 0; i < 4; i++) { float d = v[i] - mean; sq += d * d; }
    #pragma unroll
    for (int o = 16; o; o >>= 1) sq += __shfl_xor_sync(0xffffffffu, sq, o);
    if ((t & 31) == 0) red[t >> 5] = sq;
    __syncthreads();
    float sqt = 0.f;
    #pragma unroll
    for (int i = 0; i < 8; i++) sqt += red[i];
    float rstd = rsqrtf(sqt * (1.0f / (EMB - 1)) + 1e-5f);
    float4 o4; float* ov = &o4.x;
    #pragma unroll
    for (int i = 0; i < 4; i++) {
        int c = t * 4 + i;
        ov[i] = sc[c] * (v[i] - mean) * rstd + sh[c];
    }
    *(float4*)(out + (size_t)row * EMB + t * 4) = o4;
}

// ================= weight transpose + tf32 round: W[K][N] -> Wt[N][K] =================
__global__ __launch_bounds__(256)
void transpose_tf32(const float* __restrict__ W, uint32_t* __restrict__ Wt, int K, int N)
{
    __shared__ float tile[32][33];
    int x0 = blockIdx.x * 32, y0 = blockIdx.y * 32;
    int tx = threadIdx.x, ty = threadIdx.y;
    #pragma unroll
    for (int j = 0; j < 32; j += 8)
        tile[ty + j][tx] = W[(size_t)(y0 + ty + j) * N + x0 + tx];
    __syncthreads();
    #pragma unroll
    for (int j = 0; j < 32; j += 8)
        Wt[(size_t)(x0 + ty + j) * K + y0 + tx] = f2tf32(tile[tx][ty + j]);
}

// ================= tf32 mma.sync GEMM =================
// C[M,N] = A[M,K] @ Wt[N,K]^T + bias (+res | gelu).
// CTA tile 128x128, BK=32; 8 warps (2 M x 4 N), warp tile 64x32.
// SMEM rows padded to 36 floats -> conflict-free fragment LDS.
#define ASTRIDE 36
#define TILE_F  (128*ASTRIDE)              /* floats per tile buffer */
#define GEMM_SMEM (4*TILE_F*4)             /* As0,Bs0,As1,Bs1 bytes  */

__global__ __launch_bounds__(256)
void tc_gemm(const float* __restrict__ A, const uint32_t* __restrict__ Bt,
             const float* __restrict__ bias, const float* __restrict__ res,
             float* __restrict__ C, int M, int N, int K, int mode)
{
    extern __shared__ float smf[];
    float* bufA[2] = { smf,             smf + 2*TILE_F };
    float* bufB[2] = { smf + TILE_F,    smf + 3*TILE_F };

    int tid  = threadIdx.x;
    int lane = tid & 31, wid = tid >> 5;
    int g    = lane >> 2;          // group id (0..7)
    int kq   = lane & 3;           // thread-in-group (0..3)
    int wm   = wid & 1;            // warp M index (0..1)
    int wn   = wid >> 1;           // warp N index (0..3)
    int bcol = blockIdx.x * 128, brow = blockIdx.y * 128;

    // per-thread global load coords: 4 chunks of float4
    int r0[4], c0[4];
    #pragma unroll
    for (int u = 0; u < 4; u++) {
        int idx = tid + u * 256;
        r0[u] = idx >> 3;            // 0..127
        c0[u] = (idx & 7) * 4;       // 0..28
    }

    float acc[4][4][4];
    #pragma unroll
    for (int mi = 0; mi < 4; mi++)
        #pragma unroll
        for (int ni = 0; ni < 4; ni++)
            #pragma unroll
            for (int e = 0; e < 4; e++) acc[mi][ni][e] = 0.f;

    const float*    Ap = A  + (size_t)brow * K;
    const uint32_t* Bp = Bt + (size_t)bcol * K;

    int nk = K >> 5;

    float4 av[4]; uint4 bv[4];
    // prologue: load tile 0 into regs, store to buf 0
    #pragma unroll
    for (int u = 0; u < 4; u++) {
        av[u] = *(const float4*)(Ap + (size_t)r0[u] * K + c0[u]);
        bv[u] = *(const uint4*) (Bp + (size_t)r0[u] * K + c0[u]);
    }
    #pragma unroll
    for (int u = 0; u < 4; u++) {
        uint4 ta = { f2tf32(av[u].x), f2tf32(av[u].y), f2tf32(av[u].z), f2tf32(av[u].w) };
        *(uint4*)(bufA[0] + r0[u] * ASTRIDE + c0[u]) = ta;
        *(uint4*)(bufB[0] + r0[u] * ASTRIDE + c0[u]) = bv[u];
    }
    __syncthreads();

    #pragma unroll 1
    for (int kt = 0; kt < nk; kt++) {
        int cur = kt & 1;
        // issue next tile's LDGs early
        if (kt + 1 < nk) {
            const float*    Apn = Ap + (kt + 1) * 32;
            const uint32_t* Bpn = Bp + (kt + 1) * 32;
            #pragma unroll
            for (int u = 0; u < 4; u++) {
                av[u] = *(const float4*)(Apn + (size_t)r0[u] * K + c0[u]);
                bv[u] = *(const uint4*) (Bpn + (size_t)r0[u] * K + c0[u]);
            }
        }

        // compute on current buffers
        const float* As = bufA[cur];
        const float* Bs = bufB[cur];
        #pragma unroll
        for (int ks = 0; ks < 4; ks++) {
            int k0 = ks * 8 + kq;
            uint32_t af[4][4];
            #pragma unroll
            for (int mi = 0; mi < 4; mi++) {
                const float* ap = As + (wm * 64 + mi * 16 + g) * ASTRIDE;
                af[mi][0] = __float_as_uint(ap[k0]);
                af[mi][1] = __float_as_uint(ap[8 * ASTRIDE + k0]);
                af[mi][2] = __float_as_uint(ap[k0 + 4]);
                af[mi][3] = __float_as_uint(ap[8 * ASTRIDE + k0 + 4]);
            }
            uint32_t bf[4][2];
            #pragma unroll
            for (int ni = 0; ni < 4; ni++) {
                const float* bp = Bs + (wn * 32 + ni * 8 + g) * ASTRIDE;
                bf[ni][0] = __float_as_uint(bp[k0]);
                bf[ni][1] = __float_as_uint(bp[k0 + 4]);
            }
            #pragma unroll
            for (int mi = 0; mi < 4; mi++)
                #pragma unroll
                for (int ni = 0; ni < 4; ni++)
                    mma_tf32(acc[mi][ni], af[mi][0], af[mi][1], af[mi][2], af[mi][3],
                             bf[ni][0], bf[ni][1]);
        }

        // store next tile, flip
        if (kt + 1 < nk) {
            int nxt = cur ^ 1;
            #pragma unroll
            for (int u = 0; u < 4; u++) {
                uint4 ta = { f2tf32(av[u].x), f2tf32(av[u].y), f2tf32(av[u].z), f2tf32(av[u].w) };
                *(uint4*)(bufA[nxt] + r0[u] * ASTRIDE + c0[u]) = ta;
                *(uint4*)(bufB[nxt] + r0[u] * ASTRIDE + c0[u]) = bv[u];
            }
        }
        __syncthreads();
    }

    // epilogue: fragment c layout -> float2 stores
    #pragma unroll
    for (int mi = 0; mi < 4; mi++) {
        #pragma unroll
        for (int ni = 0; ni < 4; ni++) {
            int row = brow + wm * 64 + mi * 16 + g;
            int col = bcol + wn * 32 + ni * 8 + 2 * kq;
            #pragma unroll
            for (int half = 0; half < 2; half++) {
                int r = row + half * 8;
                float v0 = acc[mi][ni][half * 2 + 0] + bias[col];
                float v1 = acc[mi][ni][half * 2 + 1] + bias[col + 1];
                if (mode == 1) {
                    v0 += res[(size_t)r * N + col];
                    v1 += res[(size_t)r * N + col + 1];
                } else if (mode == 2) {
                    float x0 = v0, x1 = v1;
                    v0 = 0.5f * x0 * (1.f + tanhf(0.7978845608028654f *
                                                  (x0 + 0.044715f * x0 * x0 * x0)));
                    v1 = 0.5f * x1 * (1.f + tanhf(0.7978845608028654f *
                                                  (x1 + 0.044715f * x1 * x1 * x1)));
                }
                float2 o2 = { v0, v1 };
                *(float2*)(C + (size_t)r * N + col) = o2;
            }
        }
    }
}

// ================= Causal flash attention, fp32 SIMT =================
__global__ __launch_bounds__(256)
void attn_kernel(const float* __restrict__ Q, const float* __restrict__ K,
                 const float* __restrict__ V, float* __restrict__ O)
{
    __shared__ float Qs[64][65];
    __shared__ float Ks[32][65];
    __shared__ float Vs[32][64];
    __shared__ float Ps[64][33];

    int tid = threadIdx.x;
    int tx = tid & 15, ty = tid >> 4;
    int qb = blockIdx.x, h = blockIdx.y, b = blockIdx.z;
    size_t base = ((size_t)b * SEQ) * EMB + h * HDIM;
    const float scale = 0.125f;

    #pragma unroll
    for (int u = 0; u < 4; u++) {
        int idx = tid + u * 256;
        int r = idx >> 4, c = (idx & 15) * 4;
        float4 qv = *(const float4*)(Q + base + (size_t)(qb * 64 + r) * EMB + c);
        Qs[r][c + 0] = qv.x * scale; Qs[r][c + 1] = qv.y * scale;
        Qs[r][c + 2] = qv.z * scale; Qs[r][c + 3] = qv.w * scale;
    }

    float m_i[4], l_i[4], acc[4][4];
    #pragma unroll
    for (int i = 0; i < 4; i++) {
        m_i[i] = -1e30f; l_i[i] = 0.f;
        #pragma unroll
        for (int j = 0; j < 4; j++) acc[i][j] = 0.f;
    }

    int nkb = qb * 2 + 2;
    for (int kb = 0; kb < nkb; kb++) {
        __syncthreads();
        #pragma unroll
        for (int u = 0; u < 2; u++) {
            int idx = tid + u * 256;
            int r = idx >> 4, c = (idx & 15) * 4;
            size_t gofs = base + (size_t)(kb * 32 + r) * EMB + c;
            float4 kv = *(const float4*)(K + gofs);
            Ks[r][c + 0] = kv.x; Ks[r][c + 1] = kv.y;
            Ks[r][c + 2] = kv.z; Ks[r][c + 3] = kv.w;
            *(float4*)&Vs[r][c] = *(const float4*)(V + gofs);
        }
        __syncthreads();

        float s[4][2] = {};
        #pragma unroll
        for (int d = 0; d < 64; d++) {
            float qa[4], kr[2];
            #pragma unroll
            for (int i = 0; i < 4; i++) qa[i] = Qs[ty * 4 + i][d];
            #pragma unroll
            for (int j = 0; j < 2; j++) kr[j] = Ks[tx * 2 + j][d];
            #pragma unroll
            for (int i = 0; i < 4; i++)
                #pragma unroll
                for (int j = 0; j < 2; j++)
                    s[i][j] += qa[i] * kr[j];
        }
        #pragma unroll
        for (int i = 0; i < 4; i++)
            #pragma unroll
            for (int j = 0; j < 2; j++) {
                int qq = qb * 64 + ty * 4 + i;
                int kk = kb * 32 + tx * 2 + j;
                if (kk > qq) s[i][j] = -1e30f;
            }
        #pragma unroll
        for (int i = 0; i < 4; i++) {
            float mm = fmaxf(s[i][0], s[i][1]);
            #pragma unroll
            for (int o = 1; o < 16; o <<= 1)
                mm = fmaxf(mm, __shfl_xor_sync(0xffffffffu, mm, o));
            float mnew = fmaxf(m_i[i], mm);
            float p0 = __expf(s[i][0] - mnew);
            float p1 = __expf(s[i][1] - mnew);
            float rs = p0 + p1;
            #pragma unroll
            for (int o = 1; o < 16; o <<= 1)
                rs += __shfl_xor_sync(0xffffffffu, rs, o);
            float alpha = __expf(m_i[i] - mnew);
            l_i[i] = l_i[i] * alpha + rs;
            m_i[i] = mnew;
            #pragma unroll
            for (int j = 0; j < 4; j++) acc[i][j] *= alpha;
            Ps[ty * 4 + i][tx * 2 + 0] = p0;
            Ps[ty * 4 + i][tx * 2 + 1] = p1;
        }
        __syncthreads();
        #pragma unroll
        for (int k2 = 0; k2 < 32; k2++) {
            float pr[4], vr[4];
            #pragma unroll
            for (int i = 0; i < 4; i++) pr[i] = Ps[ty * 4 + i][k2];
            #pragma unroll
            for (int j = 0; j < 4; j++) vr[j] = Vs[k2][tx * 4 + j];
            #pragma unroll
            for (int i = 0; i < 4; i++)
                #pragma unroll
                for (int j = 0; j < 4; j++)
                    acc[i][j] += pr[i] * vr[j];
        }
    }

    #pragma unroll
    for (int i = 0; i < 4; i++) {
        float inv = 1.0f / l_i[i];
        float4 o4 = { acc[i][0] * inv, acc[i][1] * inv,
                      acc[i][2] * inv, acc[i][3] * inv };
        *(float4*)(O + base + (size_t)(qb * 64 + ty * 4 + i) * EMB + tx * 4) = o4;
    }
}

// ================= launch =================
extern "C" void kernel_launch(void* const* d_in, const int* in_sizes, int n_in,
                              void* d_out, int out_size)
{
    const float* x         = (const float*)d_in[0];
    const float* Wq        = (const float*)d_in[1];
    const float* bq        = (const float*)d_in[2];
    const float* Wk        = (const float*)d_in[3];
    const float* bk        = (const float*)d_in[4];
    const float* Wv        = (const float*)d_in[5];
    const float* bv        = (const float*)d_in[6];
    const float* Wo        = (const float*)d_in[7];
    const float* bo        = (const float*)d_in[8];
    const float* W1        = (const float*)d_in[9];
    const float* b1        = (const float*)d_in[10];
    const float* W2        = (const float*)d_in[11];
    const float* b2        = (const float*)d_in[12];
    const float* ln1_scale = (const float*)d_in[13];
    const float* ln1_shift = (const float*)d_in[14];
    const float* ln2_scale = (const float*)d_in[15];
    const float* ln2_shift = (const float*)d_in[16];
    float* out = (float*)d_out;

    float *h, *q, *k, *v, *ctx, *x2, *ff;
    uint32_t *wtq, *wtk, *wtv, *wto, *wt1, *wt2;
    cudaGetSymbolAddress((void**)&h,   g_h);
    cudaGetSymbolAddress((void**)&q,   g_q);
    cudaGetSymbolAddress((void**)&k,   g_k);
    cudaGetSymbolAddress((void**)&v,   g_v);
    cudaGetSymbolAddress((void**)&ctx, g_ctx);
    cudaGetSymbolAddress((void**)&x2,  g_x2);
    cudaGetSymbolAddress((void**)&ff,  g_ff);
    cudaGetSymbolAddress((void**)&wtq, g_wtq);
    cudaGetSymbolAddress((void**)&wtk, g_wtk);
    cudaGetSymbolAddress((void**)&wtv, g_wtv);
    cudaGetSymbolAddress((void**)&wto, g_wto);
    cudaGetSymbolAddress((void**)&wt1, g_wt1);
    cudaGetSymbolAddress((void**)&wt2, g_wt2);

    cudaFuncSetAttribute(tc_gemm, cudaFuncAttributeMaxDynamicSharedMemorySize, GEMM_SMEM);

    dim3 tb(32, 8);
    transpose_tf32<<<dim3(EMB/32, EMB/32), tb>>>(Wq, wtq, EMB, EMB);
    transpose_tf32<<<dim3(EMB/32, EMB/32), tb>>>(Wk, wtk, EMB, EMB);
    transpose_tf32<<<dim3(EMB/32, EMB/32), tb>>>(Wv, wtv, EMB, EMB);
    transpose_tf32<<<dim3(EMB/32, EMB/32), tb>>>(Wo, wto, EMB, EMB);
    transpose_tf32<<<dim3(FF/32,  EMB/32), tb>>>(W1, wt1, EMB, FF);
    transpose_tf32<<<dim3(EMB/32, FF/32),  tb>>>(W2, wt2, FF, EMB);

    dim3 gE(EMB / 128, MTOT / 128);
    dim3 gF(FF  / 128, MTOT / 128);
    dim3 gA(SEQ / 64, NHEADS, BATCH);

    ln_kernel<<<MTOT, 256>>>(x, ln1_scale, ln1_shift, h);
    tc_gemm<<<gE, 256, GEMM_SMEM>>>(h, wtq, bq, nullptr, q, MTOT, EMB, EMB, 0);
    tc_gemm<<<gE, 256, GEMM_SMEM>>>(h, wtk, bk, nullptr, k, MTOT, EMB, EMB, 0);
    tc_gemm<<<gE, 256, GEMM_SMEM>>>(h, wtv, bv, nullptr, v, MTOT, EMB, EMB, 0);
    attn_kernel<<<gA, 256>>>(q, k, v, ctx);
    tc_gemm<<<gE, 256, GEMM_SMEM>>>(ctx, wto, bo, x, x2, MTOT, EMB, EMB, 1);
    ln_kernel<<<MTOT, 256>>>(x2, ln2_scale, ln2_shift, h);
    tc_gemm<<<gF, 256, GEMM_SMEM>>>(h, wt1, b1, nullptr, ff, MTOT, FF, EMB, 2);
    tc_gemm<<<gE, 256, GEMM_SMEM>>>(ff, wt2, b2, x2, out, MTOT, EMB, FF, 1);
}

// round 4
// speedup vs baseline: 2.6212x; 1.4097x over previous
#include <cuda_runtime.h>
#include <math.h>
#include <stdint.h>

#define BATCH 2
#define SEQ   2048
#define EMB   1024
#define NHEADS 16
#define HDIM  64
#define FF    4096
#define MTOT  (BATCH*SEQ)   /* 4096 rows */

__device__ __forceinline__ uint32_t f2tf32(float x) {
    uint32_t y;
    asm("cvt.rna.tf32.f32 %0, %1;" : "=r"(y) : "f"(x));
    return y;
}
__device__ __forceinline__ void mma_tf32(float c[4],
    uint32_t a0, uint32_t a1, uint32_t a2, uint32_t a3,
    uint32_t b0, uint32_t b1)
{
    asm volatile("mma.sync.aligned.m16n8k8.row.col.f32.tf32.tf32.f32 "
        "{%0,%1,%2,%3}, {%4,%5,%6,%7}, {%8,%9}, {%0,%1,%2,%3};"
        : "+f"(c[0]), "+f"(c[1]), "+f"(c[2]), "+f"(c[3])
        : "r"(a0), "r"(a1), "r"(a2), "r"(a3), "r"(b0), "r"(b1));
}

// ================= scratch (device globals) =================
__device__ float g_h  [MTOT*EMB];
__device__ float g_q  [MTOT*EMB];
__device__ float g_k  [MTOT*EMB];
__device__ float g_v  [MTOT*EMB];
__device__ float g_ctx[MTOT*EMB];
__device__ float g_x2 [MTOT*EMB];
__device__ float g_ff [(size_t)MTOT*FF];
__device__ uint32_t g_wtq[EMB*EMB];
__device__ uint32_t g_wtk[EMB*EMB];
__device__ uint32_t g_wtv[EMB*EMB];
__device__ uint32_t g_wto[EMB*EMB];
__device__ uint32_t g_wt1[(size_t)FF*EMB];
__device__ uint32_t g_wt2[(size_t)EMB*FF];

// ================= LayerNorm (ddof=1) =================
__global__ __launch_bounds__(256)
void ln_kernel(const float* __restrict__ x, const float* __restrict__ sc,
               const float* __restrict__ sh, float* __restrict__ out)
{
    int row = blockIdx.x;
    const float* xr = x + (size_t)row * EMB;
    int t = threadIdx.x;
    float4 v4 = *(const float4*)(xr + t * 4);
    float v[4] = {v4.x, v4.y, v4.z, v4.w};
    __shared__ float red[8];
    float s = v[0] + v[1] + v[2] + v[3];
    #pragma unroll
    for (int o = 16; o; o >>= 1) s += __shfl_xor_sync(0xffffffffu, s, o);
    if ((t & 31) == 0) red[t >> 5] = s;
    __syncthreads();
    float tot = 0.f;
    #pragma unroll
    for (int i = 0; i < 8; i++) tot += red[i];
    float mean = tot * (1.0f / EMB);
    __syncthreads();
    float sq = 0.f;
    #pragma unroll
    for (int i = 0; i < 4; i++) { float d = v[i] - mean; sq += d * d; }
    #pragma unroll
    for (int o = 16; o; o >>= 1) sq += __shfl_xor_sync(0xffffffffu, sq, o);
    if ((t & 31) == 0) red[t >> 5] = sq;
    __syncthreads();
    float sqt = 0.f;
    #pragma unroll
    for (int i = 0; i < 8; i++) sqt += red[i];
    float rstd = rsqrtf(sqt * (1.0f / (EMB - 1)) + 1e-5f);
    float4 o4; float* ov = &o4.x;
    #pragma unroll
    for (int i = 0; i < 4; i++) {
        int c = t * 4 + i;
        ov[i] = sc[c] * (v[i] - mean) * rstd + sh[c];
    }
    *(float4*)(out + (size_t)row * EMB + t * 4) = o4;
}

// ================= weight transpose + tf32 round =================
__global__ __launch_bounds__(256)
void transpose_tf32(const float* __restrict__ W, uint32_t* __restrict__ Wt, int K, int N)
{
    __shared__ float tile[32][33];
    int x0 = blockIdx.x * 32, y0 = blockIdx.y * 32;
    int tx = threadIdx.x, ty = threadIdx.y;
    #pragma unroll
    for (int j = 0; j < 32; j += 8)
        tile[ty + j][tx] = W[(size_t)(y0 + ty + j) * N + x0 + tx];
    __syncthreads();
    #pragma unroll
    for (int j = 0; j < 32; j += 8)
        Wt[(size_t)(x0 + ty + j) * K + y0 + tx] = f2tf32(tile[tx][ty + j]);
}

// ================= tf32 mma.sync GEMM (unchanged from R3) =================
#define ASTRIDE 36
#define TILE_F  (128*ASTRIDE)
#define GEMM_SMEM (4*TILE_F*4)

__global__ __launch_bounds__(256)
void tc_gemm(const float* __restrict__ A, const uint32_t* __restrict__ Bt,
             const float* __restrict__ bias, const float* __restrict__ res,
             float* __restrict__ C, int M, int N, int K, int mode)
{
    extern __shared__ float smf[];
    float* bufA[2] = { smf,             smf + 2*TILE_F };
    float* bufB[2] = { smf + TILE_F,    smf + 3*TILE_F };

    int tid  = threadIdx.x;
    int lane = tid & 31, wid = tid >> 5;
    int g    = lane >> 2;
    int kq   = lane & 3;
    int wm   = wid & 1;
    int wn   = wid >> 1;
    int bcol = blockIdx.x * 128, brow = blockIdx.y * 128;

    int r0[4], c0[4];
    #pragma unroll
    for (int u = 0; u < 4; u++) {
        int idx = tid + u * 256;
        r0[u] = idx >> 3;
        c0[u] = (idx & 7) * 4;
    }

    float acc[4][4][4];
    #pragma unroll
    for (int mi = 0; mi < 4; mi++)
        #pragma unroll
        for (int ni = 0; ni < 4; ni++)
            #pragma unroll
            for (int e = 0; e < 4; e++) acc[mi][ni][e] = 0.f;

    const float*    Ap = A  + (size_t)brow * K;
    const uint32_t* Bp = Bt + (size_t)bcol * K;

    int nk = K >> 5;
    float4 av[4]; uint4 bv[4];
    #pragma unroll
    for (int u = 0; u < 4; u++) {
        av[u] = *(const float4*)(Ap + (size_t)r0[u] * K + c0[u]);
        bv[u] = *(const uint4*) (Bp + (size_t)r0[u] * K + c0[u]);
    }
    #pragma unroll
    for (int u = 0; u < 4; u++) {
        uint4 ta = { f2tf32(av[u].x), f2tf32(av[u].y), f2tf32(av[u].z), f2tf32(av[u].w) };
        *(uint4*)(bufA[0] + r0[u] * ASTRIDE + c0[u]) = ta;
        *(uint4*)(bufB[0] + r0[u] * ASTRIDE + c0[u]) = bv[u];
    }
    __syncthreads();

    #pragma unroll 1
    for (int kt = 0; kt < nk; kt++) {
        int cur = kt & 1;
        if (kt + 1 < nk) {
            const float*    Apn = Ap + (kt + 1) * 32;
            const uint32_t* Bpn = Bp + (kt + 1) * 32;
            #pragma unroll
            for (int u = 0; u < 4; u++) {
                av[u] = *(const float4*)(Apn + (size_t)r0[u] * K + c0[u]);
                bv[u] = *(const uint4*) (Bpn + (size_t)r0[u] * K + c0[u]);
            }
        }
        const float* As = bufA[cur];
        const float* Bs = bufB[cur];
        #pragma unroll
        for (int ks = 0; ks < 4; ks++) {
            int k0 = ks * 8 + kq;
            uint32_t af[4][4];
            #pragma unroll
            for (int mi = 0; mi < 4; mi++) {
                const float* ap = As + (wm * 64 + mi * 16 + g) * ASTRIDE;
                af[mi][0] = __float_as_uint(ap[k0]);
                af[mi][1] = __float_as_uint(ap[8 * ASTRIDE + k0]);
                af[mi][2] = __float_as_uint(ap[k0 + 4]);
                af[mi][3] = __float_as_uint(ap[8 * ASTRIDE + k0 + 4]);
            }
            uint32_t bf[4][2];
            #pragma unroll
            for (int ni = 0; ni < 4; ni++) {
                const float* bp = Bs + (wn * 32 + ni * 8 + g) * ASTRIDE;
                bf[ni][0] = __float_as_uint(bp[k0]);
                bf[ni][1] = __float_as_uint(bp[k0 + 4]);
            }
            #pragma unroll
            for (int mi = 0; mi < 4; mi++)
                #pragma unroll
                for (int ni = 0; ni < 4; ni++)
                    mma_tf32(acc[mi][ni], af[mi][0], af[mi][1], af[mi][2], af[mi][3],
                             bf[ni][0], bf[ni][1]);
        }
        if (kt + 1 < nk) {
            int nxt = cur ^ 1;
            #pragma unroll
            for (int u = 0; u < 4; u++) {
                uint4 ta = { f2tf32(av[u].x), f2tf32(av[u].y), f2tf32(av[u].z), f2tf32(av[u].w) };
                *(uint4*)(bufA[nxt] + r0[u] * ASTRIDE + c0[u]) = ta;
                *(uint4*)(bufB[nxt] + r0[u] * ASTRIDE + c0[u]) = bv[u];
            }
        }
        __syncthreads();
    }

    #pragma unroll
    for (int mi = 0; mi < 4; mi++) {
        #pragma unroll
        for (int ni = 0; ni < 4; ni++) {
            int row = brow + wm * 64 + mi * 16 + g;
            int col = bcol + wn * 32 + ni * 8 + 2 * kq;
            #pragma unroll
            for (int half = 0; half < 2; half++) {
                int r = row + half * 8;
                float v0 = acc[mi][ni][half * 2 + 0] + bias[col];
                float v1 = acc[mi][ni][half * 2 + 1] + bias[col + 1];
                if (mode == 1) {
                    v0 += res[(size_t)r * N + col];
                    v1 += res[(size_t)r * N + col + 1];
                } else if (mode == 2) {
                    float x0 = v0, x1 = v1;
                    v0 = 0.5f * x0 * (1.f + tanhf(0.7978845608028654f *
                                                  (x0 + 0.044715f * x0 * x0 * x0)));
                    v1 = 0.5f * x1 * (1.f + tanhf(0.7978845608028654f *
                                                  (x1 + 0.044715f * x1 * x1 * x1)));
                }
                float2 o2 = { v0, v1 };
                *(float2*)(C + (size_t)r * N + col) = o2;
            }
        }
    }
}

// ================= Causal flash attention, mma.sync tf32 =================
// CTA: 128 queries (8 warps x 16 rows), key tiles of 64, HDIM=64.
#define APAD 68
#define ATTN_SMEM ((128+64+64)*APAD*4)

__global__ __launch_bounds__(256)
void attn_mma(const float* __restrict__ Q, const float* __restrict__ K,
              const float* __restrict__ V, float* __restrict__ O)
{
    extern __shared__ float sm[];
    float* QP = sm;                    // 128 x APAD (Q staging, then P)
    float* Ks = sm + 128 * APAD;       // 64 x APAD  [key][d]
    float* Vt = Ks + 64 * APAD;        // 64 x APAD  [d][key]

    int tid = threadIdx.x, lane = tid & 31, w = tid >> 5;
    int g = lane >> 2, kq = lane & 3;
    int qb = blockIdx.x, h = blockIdx.y, b = blockIdx.z;
    size_t base = ((size_t)b * SEQ) * EMB + h * HDIM;
    int wrow = w * 16;

    // stage Q tile (pre-scaled by 1/8, tf32-rounded): 128x64
    #pragma unroll
    for (int u = 0; u < 8; u++) {
        int idx = tid + u * 256;       // 0..2047
        int r = idx >> 4, c = (idx & 15) * 4;
        float4 qv = *(const float4*)(Q + base + (size_t)(qb * 128 + r) * EMB + c);
        QP[r * APAD + c + 0] = __uint_as_float(f2tf32(qv.x * 0.125f));
        QP[r * APAD + c + 1] = __uint_as_float(f2tf32(qv.y * 0.125f));
        QP[r * APAD + c + 2] = __uint_as_float(f2tf32(qv.z * 0.125f));
        QP[r * APAD + c + 3] = __uint_as_float(f2tf32(qv.w * 0.125f));
    }
    __syncthreads();

    // Q fragments -> registers (16 rows x 64 dims per warp)
    uint32_t qa[8][4];
    #pragma unroll
    for (int ks = 0; ks < 8; ks++) {
        int k0 = ks * 8 + kq;
        qa[ks][0] = __float_as_uint(QP[(wrow + g)     * APAD + k0]);
        qa[ks][1] = __float_as_uint(QP[(wrow + g + 8) * APAD + k0]);
        qa[ks][2] = __float_as_uint(QP[(wrow + g)     * APAD + k0 + 4]);
        qa[ks][3] = __float_as_uint(QP[(wrow + g + 8) * APAD + k0 + 4]);
    }

    float m0 = -1e30f, m1 = -1e30f, l0 = 0.f, l1 = 0.f;
    float o[8][4];
    #pragma unroll
    for (int ni = 0; ni < 8; ni++)
        #pragma unroll
        for (int e = 0; e < 4; e++) o[ni][e] = 0.f;

    int nkt = 2 * qb + 2;
    #pragma unroll 1
    for (int kb = 0; kb < nkt; kb++) {
        __syncthreads();  // protect Ks/Vt (and QP on first iter: q-frags already in regs)
        // K tile 64x64 -> Ks[key][d], coalesced
        #pragma unroll
        for (int u = 0; u < 4; u++) {
            int idx = tid + u * 256;
            int r = idx >> 4, c = (idx & 15) * 4;
            float4 kv = *(const float4*)(K + base + (size_t)(kb * 64 + r) * EMB + c);
            Ks[r * APAD + c + 0] = __uint_as_float(f2tf32(kv.x));
            Ks[r * APAD + c + 1] = __uint_as_float(f2tf32(kv.y));
            Ks[r * APAD + c + 2] = __uint_as_float(f2tf32(kv.z));
            Ks[r * APAD + c + 3] = __uint_as_float(f2tf32(kv.w));
        }
        // V tile transposed -> Vt[d][key], coalesced LDG
        #pragma unroll
        for (int u = 0; u < 4; u++) {
            int chunk = tid + u * 256;
            int key = chunk >> 4, dg = (chunk & 15) * 4;
            float4 vv = *(const float4*)(V + base + (size_t)(kb * 64 + key) * EMB + dg);
            Vt[(dg + 0) * APAD + key] = __uint_as_float(f2tf32(vv.x));
            Vt[(dg + 1) * APAD + key] = __uint_as_float(f2tf32(vv.y));
            Vt[(dg + 2) * APAD + key] = __uint_as_float(f2tf32(vv.z));
            Vt[(dg + 3) * APAD + key] = __uint_as_float(f2tf32(vv.w));
        }
        __syncthreads();

        // S = Q K^T  (rows: warp's 16 queries, cols: 64 keys)
        float s[8][4];
        #pragma unroll
        for (int ni = 0; ni < 8; ni++)
            #pragma unroll
            for (int e = 0; e < 4; e++) s[ni][e] = 0.f;
        #pragma unroll
        for (int ks = 0; ks < 8; ks++) {
            int k0 = ks * 8 + kq;
            #pragma unroll
            for (int ni = 0; ni < 8; ni++) {
                uint32_t b0 = __float_as_uint(Ks[(ni * 8 + g) * APAD + k0]);
                uint32_t b1 = __float_as_uint(Ks[(ni * 8 + g) * APAD + k0 + 4]);
                mma_tf32(s[ni], qa[ks][0], qa[ks][1], qa[ks][2], qa[ks][3], b0, b1);
            }
        }

        // causal mask (only needed on the last two tiles)
        if (kb >= 2 * qb) {
            int row0 = qb * 128 + wrow + g;
            int row1 = row0 + 8;
            #pragma unroll
            for (int ni = 0; ni < 8; ni++) {
                int col = kb * 64 + ni * 8 + 2 * kq;
                if (col     > row0) s[ni][0] = -1e30f;
                if (col + 1 > row0) s[ni][1] = -1e30f;
                if (col     > row1) s[ni][2] = -1e30f;
                if (col + 1 > row1) s[ni][3] = -1e30f;
            }
        }

        // online softmax (2 rows per thread)
        float rm0 = -1e30f, rm1 = -1e30f;
        #pragma unroll
        for (int ni = 0; ni < 8; ni++) {
            rm0 = fmaxf(rm0, fmaxf(s[ni][0], s[ni][1]));
            rm1 = fmaxf(rm1, fmaxf(s[ni][2], s[ni][3]));
        }
        rm0 = fmaxf(rm0, __shfl_xor_sync(0xffffffffu, rm0, 1));
        rm0 = fmaxf(rm0, __shfl_xor_sync(0xffffffffu, rm0, 2));
        rm1 = fmaxf(rm1, __shfl_xor_sync(0xffffffffu, rm1, 1));
        rm1 = fmaxf(rm1, __shfl_xor_sync(0xffffffffu, rm1, 2));
        float mn0 = fmaxf(m0, rm0), mn1 = fmaxf(m1, rm1);
        float a0 = __expf(m0 - mn0), a1 = __expf(m1 - mn1);
        float rs0 = 0.f, rs1 = 0.f;
        #pragma unroll
        for (int ni = 0; ni < 8; ni++) {
            float p0 = __expf(s[ni][0] - mn0);
            float p1 = __expf(s[ni][1] - mn0);
            float p2 = __expf(s[ni][2] - mn1);
            float p3 = __expf(s[ni][3] - mn1);
            rs0 += p0 + p1; rs1 += p2 + p3;
            int col = ni * 8 + 2 * kq;
            float2 t0 = { __uint_as_float(f2tf32(p0)), __uint_as_float(f2tf32(p1)) };
            float2 t1 = { __uint_as_float(f2tf32(p2)), __uint_as_float(f2tf32(p3)) };
            *(float2*)(QP + (wrow + g)     * APAD + col) = t0;
            *(float2*)(QP + (wrow + g + 8) * APAD + col) = t1;
        }
        rs0 += __shfl_xor_sync(0xffffffffu, rs0, 1);
        rs0 += __shfl_xor_sync(0xffffffffu, rs0, 2);
        rs1 += __shfl_xor_sync(0xffffffffu, rs1, 1);
        rs1 += __shfl_xor_sync(0xffffffffu, rs1, 2);
        l0 = l0 * a0 + rs0;
        l1 = l1 * a1 + rs1;
        m0 = mn0; m1 = mn1;
        #pragma unroll
        for (int ni = 0; ni < 8; ni++) {
            o[ni][0] *= a0; o[ni][1] *= a0;
            o[ni][2] *= a1; o[ni][3] *= a1;
        }
        __syncwarp();

        // ctx += P @ V
        #pragma unroll
        for (int ks2 = 0; ks2 < 8; ks2++) {
            int k0 = ks2 * 8 + kq;
            uint32_t pa0 = __float_as_uint(QP[(wrow + g)     * APAD + k0]);
            uint32_t pa1 = __float_as_uint(QP[(wrow + g + 8) * APAD + k0]);
            uint32_t pa2 = __float_as_uint(QP[(wrow + g)     * APAD + k0 + 4]);
            uint32_t pa3 = __float_as_uint(QP[(wrow + g + 8) * APAD + k0 + 4]);
            #pragma unroll
            for (int ni = 0; ni < 8; ni++) {
                uint32_t b0 = __float_as_uint(Vt[(ni * 8 + g) * APAD + k0]);
                uint32_t b1 = __float_as_uint(Vt[(ni * 8 + g) * APAD + k0 + 4]);
                mma_tf32(o[ni], pa0, pa1, pa2, pa3, b0, b1);
            }
        }
    }

    // write ctx (normalized)
    float inv0 = 1.0f / l0, inv1 = 1.0f / l1;
    size_t row0 = base + (size_t)(qb * 128 + wrow + g) * EMB;
    size_t row1 = row0 + (size_t)8 * EMB;
    #pragma unroll
    for (int ni = 0; ni < 8; ni++) {
        int col = ni * 8 + 2 * kq;
        float2 q0 = { o[ni][0] * inv0, o[ni][1] * inv0 };
        float2 q1 = { o[ni][2] * inv1, o[ni][3] * inv1 };
        *(float2*)(O + row0 + col) = q0;
        *(float2*)(O + row1 + col) = q1;
    }
}

// ================= launch =================
extern "C" void kernel_launch(void* const* d_in, const int* in_sizes, int n_in,
                              void* d_out, int out_size)
{
    const float* x         = (const float*)d_in[0];
    const float* Wq        = (const float*)d_in[1];
    const float* bq        = (const float*)d_in[2];
    const float* Wk        = (const float*)d_in[3];
    const float* bk        = (const float*)d_in[4];
    const float* Wv        = (const float*)d_in[5];
    const float* bv        = (const float*)d_in[6];
    const float* Wo        = (const float*)d_in[7];
    const float* bo        = (const float*)d_in[8];
    const float* W1        = (const float*)d_in[9];
    const float* b1        = (const float*)d_in[10];
    const float* W2        = (const float*)d_in[11];
    const float* b2        = (const float*)d_in[12];
    const float* ln1_scale = (const float*)d_in[13];
    const float* ln1_shift = (const float*)d_in[14];
    const float* ln2_scale = (const float*)d_in[15];
    const float* ln2_shift = (const float*)d_in[16];
    float* out = (float*)d_out;

    float *h, *q, *k, *v, *ctx, *x2, *ff;
    uint32_t *wtq, *wtk, *wtv, *wto, *wt1, *wt2;
    cudaGetSymbolAddress((void**)&h,   g_h);
    cudaGetSymbolAddress((void**)&q,   g_q);
    cudaGetSymbolAddress((void**)&k,   g_k);
    cudaGetSymbolAddress((void**)&v,   g_v);
    cudaGetSymbolAddress((void**)&ctx, g_ctx);
    cudaGetSymbolAddress((void**)&x2,  g_x2);
    cudaGetSymbolAddress((void**)&ff,  g_ff);
    cudaGetSymbolAddress((void**)&wtq, g_wtq);
    cudaGetSymbolAddress((void**)&wtk, g_wtk);
    cudaGetSymbolAddress((void**)&wtv, g_wtv);
    cudaGetSymbolAddress((void**)&wto, g_wto);
    cudaGetSymbolAddress((void**)&wt1, g_wt1);
    cudaGetSymbolAddress((void**)&wt2, g_wt2);

    cudaFuncSetAttribute(tc_gemm,  cudaFuncAttributeMaxDynamicSharedMemorySize, GEMM_SMEM);
    cudaFuncSetAttribute(attn_mma, cudaFuncAttributeMaxDynamicSharedMemorySize, ATTN_SMEM);

    dim3 tb(32, 8);
    transpose_tf32<<<dim3(EMB/32, EMB/32), tb>>>(Wq, wtq, EMB, EMB);
    transpose_tf32<<<dim3(EMB/32, EMB/32), tb>>>(Wk, wtk, EMB, EMB);
    transpose_tf32<<<dim3(EMB/32, EMB/32), tb>>>(Wv, wtv, EMB, EMB);
    transpose_tf32<<<dim3(EMB/32, EMB/32), tb>>>(Wo, wto, EMB, EMB);
    transpose_tf32<<<dim3(FF/32,  EMB/32), tb>>>(W1, wt1, EMB, FF);
    transpose_tf32<<<dim3(EMB/32, FF/32),  tb>>>(W2, wt2, FF, EMB);

    dim3 gE(EMB / 128, MTOT / 128);
    dim3 gF(FF  / 128, MTOT / 128);
    dim3 gA(SEQ / 128, NHEADS, BATCH);

    ln_kernel<<<MTOT, 256>>>(x, ln1_scale, ln1_shift, h);
    tc_gemm<<<gE, 256, GEMM_SMEM>>>(h, wtq, bq, nullptr, q, MTOT, EMB, EMB, 0);
    tc_gemm<<<gE, 256, GEMM_SMEM>>>(h, wtk, bk, nullptr, k, MTOT, EMB, EMB, 0);
    tc_gemm<<<gE, 256, GEMM_SMEM>>>(h, wtv, bv, nullptr, v, MTOT, EMB, EMB, 0);
    attn_mma<<<gA, 256, ATTN_SMEM>>>(q, k, v, ctx);
    tc_gemm<<<gE, 256, GEMM_SMEM>>>(ctx, wto, bo, x, x2, MTOT, EMB, EMB, 1);
    ln_kernel<<<MTOT, 256>>>(x2, ln2_scale, ln2_shift, h);
    tc_gemm<<<gF, 256, GEMM_SMEM>>>(h, wt1, b1, nullptr, ff, MTOT, FF, EMB, 2);
    tc_gemm<<<gE, 256, GEMM_SMEM>>>(ff, wt2, b2, x2, out, MTOT, EMB, FF, 1);
}

// round 5
// speedup vs baseline: 3.2634x; 1.2450x over previous
#include <cuda_runtime.h>
#include <math.h>
#include <stdint.h>

#define BATCH 2
#define SEQ   2048
#define EMB   1024
#define NHEADS 16
#define HDIM  64
#define FF    4096
#define MTOT  (BATCH*SEQ)   /* 4096 rows */
#define QKVN  (3*EMB)       /* 3072 */

__device__ __forceinline__ uint32_t smem_u32(const void* p) {
    uint32_t a;
    asm("{ .reg .u64 t; cvta.to.shared.u64 t, %1; cvt.u32.u64 %0, t; }" : "=r"(a) : "l"(p));
    return a;
}
__device__ __forceinline__ uint32_t f2tf32(float x) {
    uint32_t y;
    asm("cvt.rna.tf32.f32 %0, %1;" : "=r"(y) : "f"(x));
    return y;
}
__device__ __forceinline__ float f2tf32f(float x) { return __uint_as_float(f2tf32(x)); }
__device__ __forceinline__ void mma_tf32(float c[4],
    uint32_t a0, uint32_t a1, uint32_t a2, uint32_t a3,
    uint32_t b0, uint32_t b1)
{
    asm volatile("mma.sync.aligned.m16n8k8.row.col.f32.tf32.tf32.f32 "
        "{%0,%1,%2,%3}, {%4,%5,%6,%7}, {%8,%9}, {%0,%1,%2,%3};"
        : "+f"(c[0]), "+f"(c[1]), "+f"(c[2]), "+f"(c[3])
        : "r"(a0), "r"(a1), "r"(a2), "r"(a3), "r"(b0), "r"(b1));
}
__device__ __forceinline__ void cp_async16(uint32_t saddr, const void* gptr) {
    asm volatile("cp.async.cg.shared.global [%0], [%1], 16;" :: "r"(saddr), "l"(gptr));
}
__device__ __forceinline__ void cp_commit() { asm volatile("cp.async.commit_group;" ::: "memory"); }
template<int N> __device__ __forceinline__ void cp_wait() {
    asm volatile("cp.async.wait_group %0;" :: "n"(N) : "memory");
}

// ================= scratch (device globals) =================
__device__ float g_h  [MTOT*EMB];                 // LN output, tf32-rounded
__device__ float g_qkv[(size_t)MTOT*QKVN];        // packed q|k|v, tf32-rounded
__device__ float g_ctx[MTOT*EMB];                 // attn out, tf32-rounded
__device__ float g_x2 [MTOT*EMB];                 // residual 1, full fp32
__device__ float g_ff [(size_t)MTOT*FF];          // gelu out, tf32-rounded
__device__ uint32_t g_wtqkv[(size_t)QKVN*EMB];    // [N][K] tf32
__device__ uint32_t g_wto[EMB*EMB];
__device__ uint32_t g_wt1[(size_t)FF*EMB];
__device__ uint32_t g_wt2[(size_t)EMB*FF];
__device__ float g_bqkv[QKVN];

// ================= LayerNorm (ddof=1), output tf32-rounded =================
__global__ __launch_bounds__(256)
void ln_kernel(const float* __restrict__ x, const float* __restrict__ sc,
               const float* __restrict__ sh, float* __restrict__ out)
{
    int row = blockIdx.x;
    const float* xr = x + (size_t)row * EMB;
    int t = threadIdx.x;
    float4 v4 = *(const float4*)(xr + t * 4);
    float v[4] = {v4.x, v4.y, v4.z, v4.w};
    __shared__ float red[8];
    float s = v[0] + v[1] + v[2] + v[3];
    #pragma unroll
    for (int o = 16; o; o >>= 1) s += __shfl_xor_sync(0xffffffffu, s, o);
    if ((t & 31) == 0) red[t >> 5] = s;
    __syncthreads();
    float tot = 0.f;
    #pragma unroll
    for (int i = 0; i < 8; i++) tot += red[i];
    float mean = tot * (1.0f / EMB);
    __syncthreads();
    float sq = 0.f;
    #pragma unroll
    for (int i = 0; i < 4; i++) { float d = v[i] - mean; sq += d * d; }
    #pragma unroll
    for (int o = 16; o; o >>= 1) sq += __shfl_xor_sync(0xffffffffu, sq, o);
    if ((t & 31) == 0) red[t >> 5] = sq;
    __syncthreads();
    float sqt = 0.f;
    #pragma unroll
    for (int i = 0; i < 8; i++) sqt += red[i];
    float rstd = rsqrtf(sqt * (1.0f / (EMB - 1)) + 1e-5f);
    float4 o4; float* ov = &o4.x;
    #pragma unroll
    for (int i = 0; i < 4; i++) {
        int c = t * 4 + i;
        ov[i] = f2tf32f(sc[c] * (v[i] - mean) * rstd + sh[c]);
    }
    *(float4*)(out + (size_t)row * EMB + t * 4) = o4;
}

// ================= weight transpose + tf32 round =================
__global__ __launch_bounds__(256)
void transpose_tf32(const float* __restrict__ W, uint32_t* __restrict__ Wt, int K, int N)
{
    __shared__ float tile[32][33];
    int x0 = blockIdx.x * 32, y0 = blockIdx.y * 32;
    int tx = threadIdx.x, ty = threadIdx.y;
    #pragma unroll
    for (int j = 0; j < 32; j += 8)
        tile[ty + j][tx] = W[(size_t)(y0 + ty + j) * N + x0 + tx];
    __syncthreads();
    #pragma unroll
    for (int j = 0; j < 32; j += 8)
        Wt[(size_t)(x0 + ty + j) * K + y0 + tx] = f2tf32(tile[tx][ty + j]);
}

__global__ void concat_bias(const float* a, const float* b, const float* c, float* out)
{
    int i = blockIdx.x * 256 + threadIdx.x;
    if (i < EMB)            out[i] = a[i];
    else if (i < 2 * EMB)   out[i] = b[i - EMB];
    else if (i < 3 * EMB)   out[i] = c[i - 2 * EMB];
}

// ================= tf32 mma.sync GEMM, 4-stage cp.async =================
// C[M,N] = A[M,K] @ Wt[N,K]^T + bias (+res | gelu).
// A pre-rounded tf32 floats. CTA 128x128, BK=16, 8 warps (2Mx4N), warp 64x32.
// mode 0: +bias, round out   1: +bias+res, fp32 out   2: gelu(+bias), round out
#define ROWPAD 20
#define STAGE_F (128*ROWPAD)               /* floats per operand per stage */
#define GEMM_SMEM (4*2*STAGE_F*4)          /* 81920 bytes */

__global__ __launch_bounds__(256, 2)
void tc_gemm(const float* __restrict__ A, const uint32_t* __restrict__ Bt,
             const float* __restrict__ bias, const float* __restrict__ res,
             float* __restrict__ C, int M, int N, int K, int mode)
{
    extern __shared__ float smf[];
    uint32_t sb = smem_u32(smf);

    int tid  = threadIdx.x;
    int lane = tid & 31, wid = tid >> 5;
    int g    = lane >> 2;
    int kq   = lane & 3;
    int wm   = wid & 1;
    int wn   = wid >> 1;
    int bcol = blockIdx.x * 128, brow = blockIdx.y * 128;

    const float*    Ap = A  + (size_t)brow * K;
    const uint32_t* Bp = Bt + (size_t)bcol * K;

    // per-thread load coords (2 float4 per operand per stage)
    int lr[2], lc[2];
    #pragma unroll
    for (int u = 0; u < 2; u++) {
        int idx = tid + u * 256;
        lr[u] = idx >> 2;            // 0..127
        lc[u] = (idx & 3) * 4;       // 0,4,8,12
    }

    float acc[4][4][4];
    #pragma unroll
    for (int mi = 0; mi < 4; mi++)
        #pragma unroll
        for (int ni = 0; ni < 4; ni++)
            #pragma unroll
            for (int e = 0; e < 4; e++) acc[mi][ni][e] = 0.f;

    int nk = K >> 4;

    // prologue: issue stages 0..2
    #pragma unroll
    for (int s = 0; s < 3; s++) {
        uint32_t abase = sb + (uint32_t)(s * 2 * STAGE_F) * 4;
        uint32_t bbase = abase + STAGE_F * 4;
        const float*    Ag = Ap + s * 16;
        const uint32_t* Bg = Bp + s * 16;
        #pragma unroll
        for (int u = 0; u < 2; u++) {
            cp_async16(abase + (uint32_t)(lr[u] * ROWPAD + lc[u]) * 4, Ag + (size_t)lr[u] * K + lc[u]);
            cp_async16(bbase + (uint32_t)(lr[u] * ROWPAD + lc[u]) * 4, Bg + (size_t)lr[u] * K + lc[u]);
        }
        cp_commit();
    }

    #pragma unroll 1
    for (int kt = 0; kt < nk; kt++) {
        cp_wait<2>();
        __syncthreads();

        // issue stage kt+3
        if (kt + 3 < nk) {
            int s = (kt + 3) & 3;
            uint32_t abase = sb + (uint32_t)(s * 2 * STAGE_F) * 4;
            uint32_t bbase = abase + STAGE_F * 4;
            const float*    Ag = Ap + (kt + 3) * 16;
            const uint32_t* Bg = Bp + (kt + 3) * 16;
            #pragma unroll
            for (int u = 0; u < 2; u++) {
                cp_async16(abase + (uint32_t)(lr[u] * ROWPAD + lc[u]) * 4, Ag + (size_t)lr[u] * K + lc[u]);
                cp_async16(bbase + (uint32_t)(lr[u] * ROWPAD + lc[u]) * 4, Bg + (size_t)lr[u] * K + lc[u]);
            }
        }
        cp_commit();

        const float* As = smf + (kt & 3) * 2 * STAGE_F;
        const float* Bs = As + STAGE_F;
        #pragma unroll
        for (int ks = 0; ks < 2; ks++) {
            int k0 = ks * 8 + kq;
            uint32_t af[4][4];
            #pragma unroll
            for (int mi = 0; mi < 4; mi++) {
                const float* ap = As + (wm * 64 + mi * 16 + g) * ROWPAD;
                af[mi][0] = __float_as_uint(ap[k0]);
                af[mi][1] = __float_as_uint(ap[8 * ROWPAD + k0]);
                af[mi][2] = __float_as_uint(ap[k0 + 4]);
                af[mi][3] = __float_as_uint(ap[8 * ROWPAD + k0 + 4]);
            }
            uint32_t bf[4][2];
            #pragma unroll
            for (int ni = 0; ni < 4; ni++) {
                const float* bp = Bs + (wn * 32 + ni * 8 + g) * ROWPAD;
                bf[ni][0] = __float_as_uint(bp[k0]);
                bf[ni][1] = __float_as_uint(bp[k0 + 4]);
            }
            #pragma unroll
            for (int mi = 0; mi < 4; mi++)
                #pragma unroll
                for (int ni = 0; ni < 4; ni++)
                    mma_tf32(acc[mi][ni], af[mi][0], af[mi][1], af[mi][2], af[mi][3],
                             bf[ni][0], bf[ni][1]);
        }
    }

    // epilogue
    #pragma unroll
    for (int mi = 0; mi < 4; mi++) {
        #pragma unroll
        for (int ni = 0; ni < 4; ni++) {
            int row = brow + wm * 64 + mi * 16 + g;
            int col = bcol + wn * 32 + ni * 8 + 2 * kq;
            #pragma unroll
            for (int half = 0; half < 2; half++) {
                int r = row + half * 8;
                float v0 = acc[mi][ni][half * 2 + 0] + bias[col];
                float v1 = acc[mi][ni][half * 2 + 1] + bias[col + 1];
                if (mode == 1) {
                    v0 += res[(size_t)r * N + col];
                    v1 += res[(size_t)r * N + col + 1];
                } else if (mode == 2) {
                    float x0 = v0, x1 = v1;
                    v0 = 0.5f * x0 * (1.f + tanhf(0.7978845608028654f *
                                                  (x0 + 0.044715f * x0 * x0 * x0)));
                    v1 = 0.5f * x1 * (1.f + tanhf(0.7978845608028654f *
                                                  (x1 + 0.044715f * x1 * x1 * x1)));
                }
                if (mode != 1) { v0 = f2tf32f(v0); v1 = f2tf32f(v1); }
                float2 o2 = { v0, v1 };
                *(float2*)(C + (size_t)r * N + col) = o2;
            }
        }
    }
}

// ================= Causal flash attention, mma.sync tf32 =================
// Reads packed QKV [tok][3072] (pre-rounded tf32). CTA: 128 queries, key tiles 64.
#define APAD 68
#define ATTN_SMEM ((128+64+64)*APAD*4)

__global__ __launch_bounds__(256)
void attn_mma(const float* __restrict__ QKV, float* __restrict__ O)
{
    extern __shared__ float sm[];
    float* QP = sm;                    // 128 x APAD (Q staging, then P)
    float* Ks = sm + 128 * APAD;
    float* Vt = Ks + 64 * APAD;

    int tid = threadIdx.x, lane = tid & 31, w = tid >> 5;
    int g = lane >> 2, kq = lane & 3;
    int qb = blockIdx.x, h = blockIdx.y, b = blockIdx.z;
    size_t base = ((size_t)b * SEQ) * QKVN + h * HDIM;   // q at +0, k at +EMB, v at +2*EMB
    size_t obase = ((size_t)b * SEQ) * EMB + h * HDIM;
    int wrow = w * 16;

    // stage Q tile (×0.125 is exact: no re-round needed)
    #pragma unroll
    for (int u = 0; u < 8; u++) {
        int idx = tid + u * 256;
        int r = idx >> 4, c = (idx & 15) * 4;
        float4 qv = *(const float4*)(QKV + base + (size_t)(qb * 128 + r) * QKVN + c);
        QP[r * APAD + c + 0] = qv.x * 0.125f;
        QP[r * APAD + c + 1] = qv.y * 0.125f;
        QP[r * APAD + c + 2] = qv.z * 0.125f;
        QP[r * APAD + c + 3] = qv.w * 0.125f;
    }
    __syncthreads();

    uint32_t qa[8][4];
    #pragma unroll
    for (int ks = 0; ks < 8; ks++) {
        int k0 = ks * 8 + kq;
        qa[ks][0] = __float_as_uint(QP[(wrow + g)     * APAD + k0]);
        qa[ks][1] = __float_as_uint(QP[(wrow + g + 8) * APAD + k0]);
        qa[ks][2] = __float_as_uint(QP[(wrow + g)     * APAD + k0 + 4]);
        qa[ks][3] = __float_as_uint(QP[(wrow + g + 8) * APAD + k0 + 4]);
    }

    float m0 = -1e30f, m1 = -1e30f, l0 = 0.f, l1 = 0.f;
    float o[8][4];
    #pragma unroll
    for (int ni = 0; ni < 8; ni++)
        #pragma unroll
        for (int e = 0; e < 4; e++) o[ni][e] = 0.f;

    int nkt = 2 * qb + 2;
    #pragma unroll 1
    for (int kb = 0; kb < nkt; kb++) {
        __syncthreads();
        #pragma unroll
        for (int u = 0; u < 4; u++) {
            int idx = tid + u * 256;
            int r = idx >> 4, c = (idx & 15) * 4;
            size_t gk = base + EMB + (size_t)(kb * 64 + r) * QKVN + c;
            float4 kv = *(const float4*)(QKV + gk);
            Ks[r * APAD + c + 0] = kv.x; Ks[r * APAD + c + 1] = kv.y;
            Ks[r * APAD + c + 2] = kv.z; Ks[r * APAD + c + 3] = kv.w;
        }
        #pragma unroll
        for (int u = 0; u < 4; u++) {
            int chunk = tid + u * 256;
            int key = chunk >> 4, dg = (chunk & 15) * 4;
            float4 vv = *(const float4*)(QKV + base + 2 * EMB + (size_t)(kb * 64 + key) * QKVN + dg);
            Vt[(dg + 0) * APAD + key] = vv.x;
            Vt[(dg + 1) * APAD + key] = vv.y;
            Vt[(dg + 2) * APAD + key] = vv.z;
            Vt[(dg + 3) * APAD + key] = vv.w;
        }
        __syncthreads();

        float s[8][4];
        #pragma unroll
        for (int ni = 0; ni < 8; ni++)
            #pragma unroll
            for (int e = 0; e < 4; e++) s[ni][e] = 0.f;
        #pragma unroll
        for (int ks = 0; ks < 8; ks++) {
            int k0 = ks * 8 + kq;
            #pragma unroll
            for (int ni = 0; ni < 8; ni++) {
                uint32_t b0 = __float_as_uint(Ks[(ni * 8 + g) * APAD + k0]);
                uint32_t b1 = __float_as_uint(Ks[(ni * 8 + g) * APAD + k0 + 4]);
                mma_tf32(s[ni], qa[ks][0], qa[ks][1], qa[ks][2], qa[ks][3], b0, b1);
            }
        }

        if (kb >= 2 * qb) {
            int row0 = qb * 128 + wrow + g;
            int row1 = row0 + 8;
            #pragma unroll
            for (int ni = 0; ni < 8; ni++) {
                int col = kb * 64 + ni * 8 + 2 * kq;
                if (col     > row0) s[ni][0] = -1e30f;
                if (col + 1 > row0) s[ni][1] = -1e30f;
                if (col     > row1) s[ni][2] = -1e30f;
                if (col + 1 > row1) s[ni][3] = -1e30f;
            }
        }

        float rm0 = -1e30f, rm1 = -1e30f;
        #pragma unroll
        for (int ni = 0; ni < 8; ni++) {
            rm0 = fmaxf(rm0, fmaxf(s[ni][0], s[ni][1]));
            rm1 = fmaxf(rm1, fmaxf(s[ni][2], s[ni][3]));
        }
        rm0 = fmaxf(rm0, __shfl_xor_sync(0xffffffffu, rm0, 1));
        rm0 = fmaxf(rm0, __shfl_xor_sync(0xffffffffu, rm0, 2));
        rm1 = fmaxf(rm1, __shfl_xor_sync(0xffffffffu, rm1, 1));
        rm1 = fmaxf(rm1, __shfl_xor_sync(0xffffffffu, rm1, 2));
        float mn0 = fmaxf(m0, rm0), mn1 = fmaxf(m1, rm1);
        float a0 = __expf(m0 - mn0), a1 = __expf(m1 - mn1);
        float rs0 = 0.f, rs1 = 0.f;
        #pragma unroll
        for (int ni = 0; ni < 8; ni++) {
            float p0 = __expf(s[ni][0] - mn0);
            float p1 = __expf(s[ni][1] - mn0);
            float p2 = __expf(s[ni][2] - mn1);
            float p3 = __expf(s[ni][3] - mn1);
            rs0 += p0 + p1; rs1 += p2 + p3;
            int col = ni * 8 + 2 * kq;
            float2 t0 = { f2tf32f(p0), f2tf32f(p1) };
            float2 t1 = { f2tf32f(p2), f2tf32f(p3) };
            *(float2*)(QP + (wrow + g)     * APAD + col) = t0;
            *(float2*)(QP + (wrow + g + 8) * APAD + col) = t1;
        }
        rs0 += __shfl_xor_sync(0xffffffffu, rs0, 1);
        rs0 += __shfl_xor_sync(0xffffffffu, rs0, 2);
        rs1 += __shfl_xor_sync(0xffffffffu, rs1, 1);
        rs1 += __shfl_xor_sync(0xffffffffu, rs1, 2);
        l0 = l0 * a0 + rs0;
        l1 = l1 * a1 + rs1;
        m0 = mn0; m1 = mn1;
        #pragma unroll
        for (int ni = 0; ni < 8; ni++) {
            o[ni][0] *= a0; o[ni][1] *= a0;
            o[ni][2] *= a1; o[ni][3] *= a1;
        }
        __syncwarp();

        #pragma unroll
        for (int ks2 = 0; ks2 < 8; ks2++) {
            int k0 = ks2 * 8 + kq;
            uint32_t pa0 = __float_as_uint(QP[(wrow + g)     * APAD + k0]);
            uint32_t pa1 = __float_as_uint(QP[(wrow + g + 8) * APAD + k0]);
            uint32_t pa2 = __float_as_uint(QP[(wrow + g)     * APAD + k0 + 4]);
            uint32_t pa3 = __float_as_uint(QP[(wrow + g + 8) * APAD + k0 + 4]);
            #pragma unroll
            for (int ni = 0; ni < 8; ni++) {
                uint32_t b0 = __float_as_uint(Vt[(ni * 8 + g) * APAD + k0]);
                uint32_t b1 = __float_as_uint(Vt[(ni * 8 + g) * APAD + k0 + 4]);
                mma_tf32(o[ni], pa0, pa1, pa2, pa3, b0, b1);
            }
        }
    }

    // write ctx (normalized, tf32-rounded: next GEMM consumes it via cp.async)
    float inv0 = 1.0f / l0, inv1 = 1.0f / l1;
    size_t row0 = obase + (size_t)(qb * 128 + wrow + g) * EMB;
    size_t row1 = row0 + (size_t)8 * EMB;
    #pragma unroll
    for (int ni = 0; ni < 8; ni++) {
        int col = ni * 8 + 2 * kq;
        float2 q0 = { f2tf32f(o[ni][0] * inv0), f2tf32f(o[ni][1] * inv0) };
        float2 q1 = { f2tf32f(o[ni][2] * inv1), f2tf32f(o[ni][3] * inv1) };
        *(float2*)(O + row0 + col) = q0;
        *(float2*)(O + row1 + col) = q1;
    }
}

// ================= launch =================
extern "C" void kernel_launch(void* const* d_in, const int* in_sizes, int n_in,
                              void* d_out, int out_size)
{
    const float* x         = (const float*)d_in[0];
    const float* Wq        = (const float*)d_in[1];
    const float* bq        = (const float*)d_in[2];
    const float* Wk        = (const float*)d_in[3];
    const float* bk        = (const float*)d_in[4];
    const float* Wv        = (const float*)d_in[5];
    const float* bv        = (const float*)d_in[6];
    const float* Wo        = (const float*)d_in[7];
    const float* bo        = (const float*)d_in[8];
    const float* W1        = (const float*)d_in[9];
    const float* b1        = (const float*)d_in[10];
    const float* W2        = (const float*)d_in[11];
    const float* b2        = (const float*)d_in[12];
    const float* ln1_scale = (const float*)d_in[13];
    const float* ln1_shift = (const float*)d_in[14];
    const float* ln2_scale = (const float*)d_in[15];
    const float* ln2_shift = (const float*)d_in[16];
    float* out = (float*)d_out;

    float *h, *qkv, *ctx, *x2, *ff, *bqkv;
    uint32_t *wtqkv, *wto, *wt1, *wt2;
    cudaGetSymbolAddress((void**)&h,     g_h);
    cudaGetSymbolAddress((void**)&qkv,   g_qkv);
    cudaGetSymbolAddress((void**)&ctx,   g_ctx);
    cudaGetSymbolAddress((void**)&x2,    g_x2);
    cudaGetSymbolAddress((void**)&ff,    g_ff);
    cudaGetSymbolAddress((void**)&bqkv,  g_bqkv);
    cudaGetSymbolAddress((void**)&wtqkv, g_wtqkv);
    cudaGetSymbolAddress((void**)&wto,   g_wto);
    cudaGetSymbolAddress((void**)&wt1,   g_wt1);
    cudaGetSymbolAddress((void**)&wt2,   g_wt2);

    cudaFuncSetAttribute(tc_gemm,  cudaFuncAttributeMaxDynamicSharedMemorySize, GEMM_SMEM);
    cudaFuncSetAttribute(attn_mma, cudaFuncAttributeMaxDynamicSharedMemorySize, ATTN_SMEM);

    dim3 tb(32, 8);
    transpose_tf32<<<dim3(EMB/32, EMB/32), tb>>>(Wq, wtqkv,                       EMB, EMB);
    transpose_tf32<<<dim3(EMB/32, EMB/32), tb>>>(Wk, wtqkv + (size_t)EMB*EMB,     EMB, EMB);
    transpose_tf32<<<dim3(EMB/32, EMB/32), tb>>>(Wv, wtqkv + (size_t)2*EMB*EMB,   EMB, EMB);
    transpose_tf32<<<dim3(EMB/32, EMB/32), tb>>>(Wo, wto, EMB, EMB);
    transpose_tf32<<<dim3(FF/32,  EMB/32), tb>>>(W1, wt1, EMB, FF);
    transpose_tf32<<<dim3(EMB/32, FF/32),  tb>>>(W2, wt2, FF, EMB);
    concat_bias<<<(QKVN + 255)/256, 256>>>(bq, bk, bv, bqkv);

    dim3 gQKV(QKVN / 128, MTOT / 128);
    dim3 gE  (EMB  / 128, MTOT / 128);
    dim3 gF  (FF   / 128, MTOT / 128);
    dim3 gA  (SEQ / 128, NHEADS, BATCH);

    ln_kernel<<<MTOT, 256>>>(x, ln1_scale, ln1_shift, h);
    tc_gemm<<<gQKV, 256, GEMM_SMEM>>>(h, wtqkv, bqkv, nullptr, qkv, MTOT, QKVN, EMB, 0);
    attn_mma<<<gA, 256, ATTN_SMEM>>>(qkv, ctx);
    tc_gemm<<<gE, 256, GEMM_SMEM>>>(ctx, wto, bo, x, x2, MTOT, EMB, EMB, 1);
    ln_kernel<<<MTOT, 256>>>(x2, ln2_scale, ln2_shift, h);
    tc_gemm<<<gF, 256, GEMM_SMEM>>>(h, wt1, b1, nullptr, ff, MTOT, FF, EMB, 2);
    tc_gemm<<<gE, 256, GEMM_SMEM>>>(ff, wt2, b2, x2, out, MTOT, EMB, FF, 1);
}